// round 16
// baseline (speedup 1.0000x reference)
#include <cuda_runtime.h>
#include <cuda_bf16.h>
#include <cuda_fp16.h>
#include <cstdint>

#define NN 50000
#define NE 800000
#define ET (NE + NN)
#define H 128
#define NTILES ((NN + 127) / 128)  // 391
#define PW 68

// ---------------- scratch ----------------
__device__ __half g_lin[NN * H];
__device__ float g_agg[NN * H];
__device__ float g_ssrc[NN * 4];
__device__ float g_sdst[NN * 4];
__device__ float g_bnsum[3 * 128];   // slot z zeroed by the gemm preceding attnagg z
__device__ float g_bnsum2[3 * 128];
__device__ int g_cnt[NN];            // zero-init at load; re-zeroed each call in k_mlp
__device__ int g_rowptr[NN + 1];
__device__ int g_woff[NN];
__device__ int g_csrc[ET];

// ---------------- helpers ----------------
__device__ __forceinline__ void split2(float a, float b, uint32_t& hi, uint32_t& lo) {
    __nv_bfloat16 ah = __float2bfloat16(a), bh = __float2bfloat16(b);
    __nv_bfloat16 al = __float2bfloat16(a - __bfloat162float(ah));
    __nv_bfloat16 bl = __float2bfloat16(b - __bfloat162float(bh));
    __nv_bfloat162 ph; ph.x = ah; ph.y = bh;
    __nv_bfloat162 pl; pl.x = al; pl.y = bl;
    hi = *reinterpret_cast<uint32_t*>(&ph);
    lo = *reinterpret_cast<uint32_t*>(&pl);
}
__device__ __forceinline__ void mma_bf16(float* c, uint32_t a0, uint32_t a1, uint32_t a2,
                                         uint32_t a3, uint32_t b0, uint32_t b1) {
    asm volatile(
        "mma.sync.aligned.m16n8k16.row.col.f32.bf16.bf16.f32 "
        "{%0,%1,%2,%3}, {%4,%5,%6,%7}, {%8,%9}, {%0,%1,%2,%3};"
        : "+f"(c[0]), "+f"(c[1]), "+f"(c[2]), "+f"(c[3])
        : "r"(a0), "r"(a1), "r"(a2), "r"(a3), "r"(b0), "r"(b1));
}

// ---------------- CSR build ----------------
__global__ void k_hist(const int* __restrict__ ei) {
    int e = blockIdx.x * blockDim.x + threadIdx.x;
    if (e >= NE) return;
    atomicAdd(&g_cnt[ei[NE + e]], 1);
}
__global__ void k_scan() {  // node count = g_cnt[i] + 1 (self-loop baked)
    __shared__ int sp[1024];
    const int C = (NN + 1023) / 1024;
    int t = threadIdx.x;
    int b = t * C;
    int sum = 0;
    for (int i = 0; i < C; i++) {
        int idx = b + i;
        if (idx < NN) sum += g_cnt[idx] + 1;
    }
    sp[t] = sum;
    __syncthreads();
    for (int off = 1; off < 1024; off <<= 1) {
        int v = (t >= off) ? sp[t - off] : 0;
        __syncthreads();
        sp[t] += v;
        __syncthreads();
    }
    int run = (t == 0) ? 0 : sp[t - 1];
    for (int i = 0; i < C; i++) {
        int idx = b + i;
        if (idx < NN) {
            g_rowptr[idx] = run;
            g_woff[idx] = run;
            run += g_cnt[idx] + 1;
        }
    }
    if (t == 1023) g_rowptr[NN] = run;
}
__global__ void k_scatter(const int* __restrict__ ei) {
    int e = blockIdx.x * blockDim.x + threadIdx.x;
    if (e >= ET) return;
    int s, d;
    if (e < NE) { s = ei[e]; d = ei[NE + e]; } else { s = d = e - NE; }
    g_csrc[atomicAdd(&g_woff[d], 1)] = s;
}

// ---------------- tensor-core GAT GEMM: M128 tile, 512 threads (16 warps) ----------------
#define GSMEM_BYTES (4 * 128 * PW * 4)
template <int HEADS, bool FUSE_IN>
__global__ void __launch_bounds__(512, 1) k_gemm_tc(const float* __restrict__ W,
                                                    const float* __restrict__ a_s,
                                                    const float* __restrict__ a_d,
                                                    const float* __restrict__ x,
                                                    const float* __restrict__ W_in,
                                                    const float* __restrict__ b_in,
                                                    const float* __restrict__ gam,
                                                    const float* __restrict__ bet,
                                                    int slot, int zslot) {
    extern __shared__ uint32_t smem_u[];
    uint32_t* sWhi = smem_u;
    uint32_t* sWlo = smem_u + 128 * PW;
    uint32_t* sAhi = smem_u + 2 * 128 * PW;
    uint32_t* sAlo = smem_u + 3 * 128 * PW;
    __shared__ float s_as[128], s_ad[128];
    __shared__ float s_red[2][128][4];
    __shared__ float s_sc[128], s_sh[128];
    __shared__ float s_xin[128 * 5];
    __shared__ float s_win[128 * 5];
    __shared__ float s_bin[128];

    const int tid = threadIdx.x;
    const int wid = tid >> 5, lane = tid & 31;
    const int warpM = wid >> 2, warpN = wid & 3;  // 4 x 4 warp grid
    const int g = lane >> 2, q = lane & 3;

    if (blockIdx.x == 0 && tid < 128) {
        g_bnsum[zslot * 128 + tid] = 0.f;
        g_bnsum2[zslot * 128 + tid] = 0.f;
    }
    if (tid < 128) {
        s_as[tid] = a_s[tid];
        s_ad[tid] = a_d[tid];
        if (FUSE_IN) {
            s_bin[tid] = b_in[tid];
        } else {
            float mu = g_bnsum[slot * 128 + tid] * (1.f / NN);
            float var = g_bnsum2[slot * 128 + tid] * (1.f / NN) - mu * mu;
            float sc = gam[tid] * rsqrtf(var + 1e-5f);
            s_sc[tid] = sc;
            s_sh[tid] = bet[tid] - mu * sc;
        }
    }
    if (FUSE_IN) {
        for (int i = tid; i < 640; i += 512) s_win[i] = W_in[i];
    }
    // convert W (128x128): row = tid>>2, 32 cols per thread
    {
        const int row = tid >> 2;
        const int ch = (tid & 3) * 32;
#pragma unroll 4
        for (int i = 0; i < 8; i++) {
            int col = ch + i * 4;
            float4 v = *reinterpret_cast<const float4*>(&W[row * 128 + col]);
            uint32_t h0, l0, h1, l1;
            split2(v.x, v.y, h0, l0);
            split2(v.z, v.w, h1, l1);
            int widx = row * PW + (col >> 1);
            *reinterpret_cast<uint2*>(&sWhi[widx]) = make_uint2(h0, h1);
            *reinterpret_cast<uint2*>(&sWlo[widx]) = make_uint2(l0, l1);
        }
    }

    for (int tile = blockIdx.x; tile < NTILES; tile += gridDim.x) {
        const int node0 = tile * 128;
        __syncthreads();
        if (FUSE_IN) {
            for (int i = tid; i < 640; i += 512) {
                int gi = node0 * 5 + i;
                s_xin[i] = (gi < NN * 5) ? x[gi] : 0.f;
            }
            __syncthreads();
        }
        // build A tile: row = tid>>2, 32 cols per thread
        {
            const int row = tid >> 2;
            const int ch = (tid & 3) * 32;
            const int node = node0 + row;
            float x5[5];
            if (FUSE_IN) {
#pragma unroll
                for (int k = 0; k < 5; k++) x5[k] = s_xin[row * 5 + k];
            }
#pragma unroll 4
            for (int i = 0; i < 8; i++) {
                int col = ch + i * 4;
                float4 v;
                if (FUSE_IN) {
                    float c4[4];
#pragma unroll
                    for (int c = 0; c < 4; c++) {
                        float acc = s_bin[col + c];
#pragma unroll
                        for (int k = 0; k < 5; k++)
                            acc = fmaf(x5[k], s_win[(col + c) * 5 + k], acc);
                        c4[c] = fmaxf(acc, 0.f);
                    }
                    v = make_float4(c4[0], c4[1], c4[2], c4[3]);
                } else {
                    v = (node < NN) ? *reinterpret_cast<const float4*>(&g_agg[node * 128 + col])
                                    : make_float4(0.f, 0.f, 0.f, 0.f);
                    v.x = fmaxf(fmaf(v.x, s_sc[col + 0], s_sh[col + 0]), 0.f);
                    v.y = fmaxf(fmaf(v.y, s_sc[col + 1], s_sh[col + 1]), 0.f);
                    v.z = fmaxf(fmaf(v.z, s_sc[col + 2], s_sh[col + 2]), 0.f);
                    v.w = fmaxf(fmaf(v.w, s_sc[col + 3], s_sh[col + 3]), 0.f);
                }
                uint32_t h0, l0, h1, l1;
                split2(v.x, v.y, h0, l0);
                split2(v.z, v.w, h1, l1);
                int widx = row * PW + (col >> 1);
                *reinterpret_cast<uint2*>(&sAhi[widx]) = make_uint2(h0, h1);
                *reinterpret_cast<uint2*>(&sAlo[widx]) = make_uint2(l0, l1);
            }
        }
        __syncthreads();

        // MMA: each warp 32 rows x 32 cols
        float acc[2][4][4];
#pragma unroll
        for (int mt = 0; mt < 2; mt++)
#pragma unroll
            for (int nt = 0; nt < 4; nt++)
#pragma unroll
                for (int i = 0; i < 4; i++) acc[mt][nt][i] = 0.f;

#pragma unroll
        for (int ks = 0; ks < 8; ks++) {
            const int kw = ks * 8 + q;
            uint32_t bh[4][2], bl[4][2];
#pragma unroll
            for (int nt = 0; nt < 4; nt++) {
                int ro = warpN * 32 + nt * 8 + g;
                int bidx = ro * PW + kw;
                bh[nt][0] = sWhi[bidx];
                bh[nt][1] = sWhi[bidx + 4];
                bl[nt][0] = sWlo[bidx];
                bl[nt][1] = sWlo[bidx + 4];
            }
#pragma unroll
            for (int mt = 0; mt < 2; mt++) {
                int ra = warpM * 32 + mt * 16 + g;
                int aidx = ra * PW + kw;
                uint32_t ah0 = sAhi[aidx], ah1 = sAhi[aidx + 8 * PW];
                uint32_t ah2 = sAhi[aidx + 4], ah3 = sAhi[aidx + 8 * PW + 4];
                uint32_t al0 = sAlo[aidx], al1 = sAlo[aidx + 8 * PW];
                uint32_t al2 = sAlo[aidx + 4], al3 = sAlo[aidx + 8 * PW + 4];
#pragma unroll
                for (int nt = 0; nt < 4; nt++) {
                    mma_bf16(acc[mt][nt], ah0, ah1, ah2, ah3, bh[nt][0], bh[nt][1]);
                    mma_bf16(acc[mt][nt], ah0, ah1, ah2, ah3, bl[nt][0], bl[nt][1]);
                    mma_bf16(acc[mt][nt], al0, al1, al2, al3, bh[nt][0], bh[nt][1]);
                }
            }
        }

        // epilogue: g_lin (fp16) + attention dots (warpN quadrant = 1 head for HEADS4)
        float ats[4], atd[4];
#pragma unroll
        for (int s2 = 0; s2 < 4; s2++) { ats[s2] = 0.f; atd[s2] = 0.f; }
#pragma unroll
        for (int mt = 0; mt < 2; mt++) {
            const int r0 = warpM * 32 + mt * 16 + g;
            const int na = node0 + r0, nb = node0 + r0 + 8;
#pragma unroll
            for (int nt = 0; nt < 4; nt++) {
                const int colb = warpN * 32 + nt * 8 + q * 2;
                const float* a4 = acc[mt][nt];
                ats[mt * 2 + 0] += a4[0] * s_as[colb] + a4[1] * s_as[colb + 1];
                atd[mt * 2 + 0] += a4[0] * s_ad[colb] + a4[1] * s_ad[colb + 1];
                ats[mt * 2 + 1] += a4[2] * s_as[colb] + a4[3] * s_as[colb + 1];
                atd[mt * 2 + 1] += a4[2] * s_ad[colb] + a4[3] * s_ad[colb + 1];
                if (na < NN)
                    *reinterpret_cast<__half2*>(&g_lin[na * 128 + colb]) =
                        __floats2half2_rn(a4[0], a4[1]);
                if (nb < NN)
                    *reinterpret_cast<__half2*>(&g_lin[nb * 128 + colb]) =
                        __floats2half2_rn(a4[2], a4[3]);
            }
        }
#pragma unroll
        for (int o = 1; o <= 2; o <<= 1) {
#pragma unroll
            for (int s2 = 0; s2 < 4; s2++) {
                ats[s2] += __shfl_xor_sync(0xffffffffu, ats[s2], o);
                atd[s2] += __shfl_xor_sync(0xffffffffu, atd[s2], o);
            }
        }
        if (HEADS == 4) {
            if (q == 0) {
#pragma unroll
                for (int s2 = 0; s2 < 4; s2++) {
                    int row = warpM * 32 + s2 * 8 + g;
                    int node = node0 + row;
                    if (node < NN) {
                        g_ssrc[node * 4 + warpN] = ats[s2];
                        g_sdst[node * 4 + warpN] = atd[s2];
                    }
                }
            }
        } else {
            if (q == 0) {
#pragma unroll
                for (int s2 = 0; s2 < 4; s2++) {
                    int row = warpM * 32 + s2 * 8 + g;
                    s_red[0][row][warpN] = ats[s2];
                    s_red[1][row][warpN] = atd[s2];
                }
            }
            __syncthreads();
            if (tid < 128) {
                int node = node0 + tid;
                if (node < NN) {
                    g_ssrc[node] = s_red[0][tid][0] + s_red[0][tid][1] +
                                   s_red[0][tid][2] + s_red[0][tid][3];
                    g_sdst[node] = s_red[1][tid][0] + s_red[1][tid][1] +
                                   s_red[1][tid][2] + s_red[1][tid][3];
                }
            }
        }
    }
}

// ---------------- fused attention + aggregation + BN stats (R12 version) ----------------
template <int HEADS>
__global__ void k_attnagg(int slot) {
    __shared__ float bsum[128], bsum2[128];
    const int tid = threadIdx.x;
    if (tid < 128) {
        bsum[tid] = 0.f;
        bsum2[tid] = 0.f;
    }
    __syncthreads();

    const int w = (blockIdx.x * blockDim.x + tid) >> 5;
    const int lane = tid & 31;
    if (w < NN) {
        const int beg = g_rowptr[w];
        const int end = g_rowptr[w + 1];

        float4 sd;
        if (HEADS == 4) sd = *reinterpret_cast<const float4*>(&g_sdst[w * 4]);
        else sd.x = g_sdst[w];

        const int hd = lane >> 3;
        float4 sume = make_float4(0.f, 0.f, 0.f, 0.f);
        float4 acc = make_float4(0.f, 0.f, 0.f, 0.f);
        for (int base = beg; base < end; base += 32) {
            const int i = base + lane;
            int s = 0;
            float4 ev = make_float4(0.f, 0.f, 0.f, 0.f);
            if (i < end) {
                s = g_csrc[i];
                if (HEADS == 4) {
                    float4 vs = *reinterpret_cast<const float4*>(&g_ssrc[s * 4]);
                    float lx = vs.x + sd.x; lx = lx > 0.f ? lx : 0.2f * lx;
                    float ly = vs.y + sd.y; ly = ly > 0.f ? ly : 0.2f * ly;
                    float lz = vs.z + sd.z; lz = lz > 0.f ? lz : 0.2f * lz;
                    float lw = vs.w + sd.w; lw = lw > 0.f ? lw : 0.2f * lw;
                    ev.x = __expf(lx); ev.y = __expf(ly);
                    ev.z = __expf(lz); ev.w = __expf(lw);
                    sume.x += ev.x; sume.y += ev.y; sume.z += ev.z; sume.w += ev.w;
                } else {
                    float l = g_ssrc[s] + sd.x;
                    l = l > 0.f ? l : 0.2f * l;
                    ev.x = __expf(l);
                    sume.x += ev.x;
                }
            }
            const int cnt = min(32, end - base);
            for (int j = 0; j < cnt; j++) {
                int sj = __shfl_sync(0xffffffffu, s, j);
                float evh;
                if (HEADS == 4) {
                    float e0 = __shfl_sync(0xffffffffu, ev.x, j);
                    float e1 = __shfl_sync(0xffffffffu, ev.y, j);
                    float e2 = __shfl_sync(0xffffffffu, ev.z, j);
                    float e3 = __shfl_sync(0xffffffffu, ev.w, j);
                    evh = (hd == 0) ? e0 : (hd == 1) ? e1 : (hd == 2) ? e2 : e3;
                } else {
                    evh = __shfl_sync(0xffffffffu, ev.x, j);
                }
                uint2 raw = *reinterpret_cast<const uint2*>(&g_lin[sj * 128 + lane * 4]);
                float2 f01 = __half22float2(*reinterpret_cast<__half2*>(&raw.x));
                float2 f23 = __half22float2(*reinterpret_cast<__half2*>(&raw.y));
                acc.x = fmaf(evh, f01.x, acc.x);
                acc.y = fmaf(evh, f01.y, acc.y);
                acc.z = fmaf(evh, f23.x, acc.z);
                acc.w = fmaf(evh, f23.y, acc.w);
            }
        }
#pragma unroll
        for (int o = 16; o > 0; o >>= 1) {
            sume.x += __shfl_xor_sync(0xffffffffu, sume.x, o);
            if (HEADS == 4) {
                sume.y += __shfl_xor_sync(0xffffffffu, sume.y, o);
                sume.z += __shfl_xor_sync(0xffffffffu, sume.z, o);
                sume.w += __shfl_xor_sync(0xffffffffu, sume.w, o);
            }
        }
        float dh;
        if (HEADS == 4)
            dh = (hd == 0) ? sume.x : (hd == 1) ? sume.y : (hd == 2) ? sume.z : sume.w;
        else
            dh = sume.x;
        float inv = 1.f / (dh + 1e-16f);
        acc.x *= inv; acc.y *= inv; acc.z *= inv; acc.w *= inv;
        *reinterpret_cast<float4*>(&g_agg[w * 128 + lane * 4]) = acc;

        const int c0 = lane * 4;
        atomicAdd(&bsum[c0 + 0], acc.x);
        atomicAdd(&bsum[c0 + 1], acc.y);
        atomicAdd(&bsum[c0 + 2], acc.z);
        atomicAdd(&bsum[c0 + 3], acc.w);
        atomicAdd(&bsum2[c0 + 0], acc.x * acc.x);
        atomicAdd(&bsum2[c0 + 1], acc.y * acc.y);
        atomicAdd(&bsum2[c0 + 2], acc.z * acc.z);
        atomicAdd(&bsum2[c0 + 3], acc.w * acc.w);
    }
    __syncthreads();
    if (tid < 128) {
        atomicAdd(&g_bnsum[slot * 128 + tid], bsum[tid]);
        atomicAdd(&g_bnsum2[slot * 128 + tid], bsum2[tid]);
    }
}

// ---------------- fused MLP head (+ resets g_cnt for next call) ----------------
__global__ void k_mlp(const float* __restrict__ W1, const float* __restrict__ b1,
                      const float* __restrict__ W2, const float* __restrict__ b2,
                      const float* __restrict__ gam, const float* __restrict__ bet,
                      float* __restrict__ out) {
    __shared__ float sW[64 * 129];
    __shared__ float sx[128 * 8];
    __shared__ float s_sc[128], s_sh[128];
    __shared__ float s_part[2][8];
    const int tid = threadIdx.x;  // 64
    const int wrp = tid >> 5, lane = tid & 31;
    for (int i = blockIdx.x * 64 + tid; i < NN; i += gridDim.x * 64) g_cnt[i] = 0;
    for (int idx = tid; idx < 64 * 128; idx += 64) {
        int t = idx >> 7, k = idx & 127;
        sW[t * 129 + k] = W1[idx];
    }
    for (int idx = tid; idx < 128; idx += 64) {
        float mu = g_bnsum[2 * 128 + idx] * (1.f / NN);
        float var = g_bnsum2[2 * 128 + idx] * (1.f / NN) - mu * mu;
        float sc = gam[idx] * rsqrtf(var + 1e-5f);
        s_sc[idx] = sc;
        s_sh[idx] = bet[idx] - mu * sc;
    }
    const float bias = b1[tid];
    const float w2 = W2[tid];
    const float b2v = b2[0];
    __syncthreads();
    const int NCH = NN / 8;
    for (int chunk = blockIdx.x; chunk < NCH; chunk += gridDim.x) {
        const int n0 = chunk * 8;
        __syncthreads();
#pragma unroll
        for (int nb = 0; nb < 8; nb++)
            for (int k = tid; k < 128; k += 64)
                sx[k * 8 + nb] = fmaf(g_agg[(n0 + nb) * 128 + k], s_sc[k], s_sh[k]);
        __syncthreads();
        float acc[8];
#pragma unroll
        for (int i = 0; i < 8; i++) acc[i] = 0.f;
#pragma unroll 4
        for (int k = 0; k < 128; k++) {
            float w = sW[tid * 129 + k];
            float4 xa = *reinterpret_cast<float4*>(&sx[k * 8]);
            float4 xb = *reinterpret_cast<float4*>(&sx[k * 8 + 4]);
            acc[0] = fmaf(w, xa.x, acc[0]);
            acc[1] = fmaf(w, xa.y, acc[1]);
            acc[2] = fmaf(w, xa.z, acc[2]);
            acc[3] = fmaf(w, xa.w, acc[3]);
            acc[4] = fmaf(w, xb.x, acc[4]);
            acc[5] = fmaf(w, xb.y, acc[5]);
            acc[6] = fmaf(w, xb.z, acc[6]);
            acc[7] = fmaf(w, xb.w, acc[7]);
        }
        float c8[8];
#pragma unroll
        for (int nb = 0; nb < 8; nb++) c8[nb] = fmaxf(acc[nb] + bias, 0.f) * w2;
#pragma unroll
        for (int o = 16; o > 0; o >>= 1)
#pragma unroll
            for (int nb = 0; nb < 8; nb++)
                c8[nb] += __shfl_xor_sync(0xffffffffu, c8[nb], o);
        if (lane == 0)
#pragma unroll
            for (int nb = 0; nb < 8; nb++) s_part[wrp][nb] = c8[nb];
        __syncthreads();
        if (tid < 8) out[n0 + tid] = s_part[0][tid] + s_part[1][tid] + b2v;
    }
}

// ---------------- launch ----------------
extern "C" void kernel_launch(void* const* d_in, const int* in_sizes, int n_in,
                              void* d_out, int out_size) {
    const float* x    = (const float*)d_in[0];
    const int*   ei   = (const int*)d_in[1];
    const float* W_in = (const float*)d_in[2];
    const float* b_in = (const float*)d_in[3];
    const float* Wl[3]  = {(const float*)d_in[4], (const float*)d_in[8], (const float*)d_in[12]};
    const float* ASl[3] = {(const float*)d_in[5], (const float*)d_in[9], (const float*)d_in[13]};
    const float* ADl[3] = {(const float*)d_in[6], (const float*)d_in[10], (const float*)d_in[14]};
    // GAT biases b0/b1/b2 cancel exactly in the following BatchNorm
    const float* Gl[3]  = {(const float*)d_in[16], (const float*)d_in[18], (const float*)d_in[20]};
    const float* Bl[3]  = {(const float*)d_in[17], (const float*)d_in[19], (const float*)d_in[21]};
    const float* Wc1 = (const float*)d_in[22];
    const float* bc1 = (const float*)d_in[23];
    const float* Wc2 = (const float*)d_in[24];
    const float* bc2 = (const float*)d_in[25];
    float* out = (float*)d_out;

    cudaFuncSetAttribute(k_gemm_tc<4, true>, cudaFuncAttributeMaxDynamicSharedMemorySize, GSMEM_BYTES);
    cudaFuncSetAttribute(k_gemm_tc<4, false>, cudaFuncAttributeMaxDynamicSharedMemorySize, GSMEM_BYTES);
    cudaFuncSetAttribute(k_gemm_tc<1, false>, cudaFuncAttributeMaxDynamicSharedMemorySize, GSMEM_BYTES);

    const int EB = 256;
    const int EG = (ET + EB - 1) / EB;
    const int HG = (NE + EB - 1) / EB;
    const int AGG_BLOCKS = NN * 32 / EB;  // 6250

    k_hist<<<HG, EB>>>(ei);
    k_scan<<<1, 1024>>>();
    k_scatter<<<EG, EB>>>(ei);

    // layer 0 (input layer fused; zeroes BN slot 0)
    k_gemm_tc<4, true><<<148, 512, GSMEM_BYTES>>>(Wl[0], ASl[0], ADl[0], x, W_in, b_in,
                                                  nullptr, nullptr, 0, 0);
    k_attnagg<4><<<AGG_BLOCKS, EB>>>(0);
    // layer 1 (reads BN slot 0; zeroes slot 1)
    k_gemm_tc<4, false><<<148, 512, GSMEM_BYTES>>>(Wl[1], ASl[1], ADl[1], x, W_in, b_in,
                                                   Gl[0], Bl[0], 0, 1);
    k_attnagg<4><<<AGG_BLOCKS, EB>>>(1);
    // layer 2 (reads slot 1; zeroes slot 2)
    k_gemm_tc<1, false><<<148, 512, GSMEM_BYTES>>>(Wl[2], ASl[2], ADl[2], x, W_in, b_in,
                                                   Gl[1], Bl[1], 1, 2);
    k_attnagg<1><<<AGG_BLOCKS, EB>>>(2);
    // fused MLP head (reads slot 2; resets g_cnt for next call)
    k_mlp<<<1024, 64>>>(Wc1, bc1, Wc2, bc2, Gl[2], Bl[2], out);
}

// round 17
// speedup vs baseline: 1.0431x; 1.0431x over previous
#include <cuda_runtime.h>
#include <cuda_bf16.h>
#include <cuda_fp16.h>
#include <cstdint>

#define NN 50000
#define NE 800000
#define ET (NE + NN)
#define H 128
#define NTILES ((NN + 127) / 128)  // 391
#define PW 68

// ---------------- scratch ----------------
__device__ __half g_lin[NN * H];
__device__ float g_agg[NN * H];
__device__ float g_ssrc[NN * 4];
__device__ float g_sdst[NN * 4];
__device__ float g_bnsum[3 * 128];   // slot z zeroed by the gemm preceding attnagg z
__device__ float g_bnsum2[3 * 128];
__device__ int g_cnt[NN];            // zero-init at load; re-zeroed each call in k_mlp
__device__ int g_rowptr[NN + 1];
__device__ int g_woff[NN];
__device__ int g_csrc[ET];

// ---------------- helpers ----------------
__device__ __forceinline__ void split2(float a, float b, uint32_t& hi, uint32_t& lo) {
    __nv_bfloat16 ah = __float2bfloat16(a), bh = __float2bfloat16(b);
    __nv_bfloat16 al = __float2bfloat16(a - __bfloat162float(ah));
    __nv_bfloat16 bl = __float2bfloat16(b - __bfloat162float(bh));
    __nv_bfloat162 ph; ph.x = ah; ph.y = bh;
    __nv_bfloat162 pl; pl.x = al; pl.y = bl;
    hi = *reinterpret_cast<uint32_t*>(&ph);
    lo = *reinterpret_cast<uint32_t*>(&pl);
}
__device__ __forceinline__ void mma_bf16(float* c, uint32_t a0, uint32_t a1, uint32_t a2,
                                         uint32_t a3, uint32_t b0, uint32_t b1) {
    asm volatile(
        "mma.sync.aligned.m16n8k16.row.col.f32.bf16.bf16.f32 "
        "{%0,%1,%2,%3}, {%4,%5,%6,%7}, {%8,%9}, {%0,%1,%2,%3};"
        : "+f"(c[0]), "+f"(c[1]), "+f"(c[2]), "+f"(c[3])
        : "r"(a0), "r"(a1), "r"(a2), "r"(a3), "r"(b0), "r"(b1));
}
#define LDSM_X4(r0, r1, r2, r3, addr)                                         \
    asm volatile("ldmatrix.sync.aligned.m8n8.x4.shared.b16 {%0,%1,%2,%3}, [%4];" \
                 : "=r"(r0), "=r"(r1), "=r"(r2), "=r"(r3) : "r"(addr))
__device__ __forceinline__ uint32_t smem_addr(const void* p) {
    return (uint32_t)__cvta_generic_to_shared(p);
}

// ---------------- CSR build ----------------
__global__ void k_hist(const int* __restrict__ ei) {
    int e = blockIdx.x * blockDim.x + threadIdx.x;
    if (e >= NE) return;
    atomicAdd(&g_cnt[ei[NE + e]], 1);
}
__global__ void k_scan() {  // node count = g_cnt[i] + 1 (self-loop baked)
    __shared__ int sp[1024];
    const int C = (NN + 1023) / 1024;
    int t = threadIdx.x;
    int b = t * C;
    int sum = 0;
    for (int i = 0; i < C; i++) {
        int idx = b + i;
        if (idx < NN) sum += g_cnt[idx] + 1;
    }
    sp[t] = sum;
    __syncthreads();
    for (int off = 1; off < 1024; off <<= 1) {
        int v = (t >= off) ? sp[t - off] : 0;
        __syncthreads();
        sp[t] += v;
        __syncthreads();
    }
    int run = (t == 0) ? 0 : sp[t - 1];
    for (int i = 0; i < C; i++) {
        int idx = b + i;
        if (idx < NN) {
            g_rowptr[idx] = run;
            g_woff[idx] = run;
            run += g_cnt[idx] + 1;
        }
    }
    if (t == 1023) g_rowptr[NN] = run;
}
__global__ void k_scatter(const int* __restrict__ ei) {
    int e = blockIdx.x * blockDim.x + threadIdx.x;
    if (e >= ET) return;
    int s, d;
    if (e < NE) { s = ei[e]; d = ei[NE + e]; } else { s = d = e - NE; }
    g_csrc[atomicAdd(&g_woff[d], 1)] = s;
}

// ---------------- tensor-core GAT GEMM (256 thr, M128, ldmatrix fragments) ----------------
#define GSMEM_BYTES (4 * 128 * PW * 4)
template <int HEADS, bool FUSE_IN>
__global__ void __launch_bounds__(256, 1) k_gemm_tc(const float* __restrict__ W,
                                                    const float* __restrict__ a_s,
                                                    const float* __restrict__ a_d,
                                                    const float* __restrict__ x,
                                                    const float* __restrict__ W_in,
                                                    const float* __restrict__ b_in,
                                                    const float* __restrict__ gam,
                                                    const float* __restrict__ bet,
                                                    int slot, int zslot) {
    extern __shared__ uint32_t smem_u[];
    uint32_t* sWhi = smem_u;
    uint32_t* sWlo = smem_u + 128 * PW;
    uint32_t* sAhi = smem_u + 2 * 128 * PW;
    uint32_t* sAlo = smem_u + 3 * 128 * PW;
    __shared__ float s_as[128], s_ad[128];
    __shared__ float s_red[2][128][2];
    __shared__ float s_sc[128], s_sh[128];
    __shared__ float s_xin[128 * 5];
    __shared__ float s_win[128 * 5];
    __shared__ float s_bin[128];

    const int tid = threadIdx.x;
    const int wid = tid >> 5, lane = tid & 31;
    const int warpM = wid >> 1, warpN = wid & 1;
    const int g = lane >> 2, q = lane & 3;

    if (blockIdx.x == 0 && tid < 128) {
        g_bnsum[zslot * 128 + tid] = 0.f;
        g_bnsum2[zslot * 128 + tid] = 0.f;
    }
    if (tid < 128) {
        s_as[tid] = a_s[tid];
        s_ad[tid] = a_d[tid];
        if (FUSE_IN) {
            s_bin[tid] = b_in[tid];
        } else {
            float mu = g_bnsum[slot * 128 + tid] * (1.f / NN);
            float var = g_bnsum2[slot * 128 + tid] * (1.f / NN) - mu * mu;
            float sc = gam[tid] * rsqrtf(var + 1e-5f);
            s_sc[tid] = sc;
            s_sh[tid] = bet[tid] - mu * sc;
        }
    }
    if (FUSE_IN) {
        for (int i = tid; i < 640; i += 256) s_win[i] = W_in[i];
    }
    // convert W once per CTA
    {
        const int row = tid >> 1;
        const int ch = (tid & 1) * 64;
#pragma unroll 4
        for (int i = 0; i < 16; i++) {
            int col = ch + i * 4;
            float4 v = *reinterpret_cast<const float4*>(&W[row * 128 + col]);
            uint32_t h0, l0, h1, l1;
            split2(v.x, v.y, h0, l0);
            split2(v.z, v.w, h1, l1);
            int widx = row * PW + (col >> 1);
            *reinterpret_cast<uint2*>(&sWhi[widx]) = make_uint2(h0, h1);
            *reinterpret_cast<uint2*>(&sWlo[widx]) = make_uint2(l0, l1);
        }
    }

    // precompute ldmatrix lane addresses (byte addresses in shared space)
    const uint32_t baseW = smem_addr(sWhi);  // sWlo = +128*PW*4, sAhi = +2*.., sAlo = +3*..
    const uint32_t WLO = 128 * PW * 4;
    // A: row = warpM*32 + mt*16 + (lane&15); k-half = lane>>4
    uint32_t aAddr[2];
#pragma unroll
    for (int mt = 0; mt < 2; mt++) {
        int row = warpM * 32 + mt * 16 + (lane & 15);
        aAddr[mt] = baseW + 2 * WLO + row * (PW * 4) + (lane >> 4) * 16;
    }
    // B pairs: tiles 2*ntp, 2*ntp+1; row(col) = warpN*64 + ntp*16 + ((lane>>4)&1)*8 + (lane&7);
    // k-half = (lane>>3)&1
    uint32_t bAddr[4];
#pragma unroll
    for (int ntp = 0; ntp < 4; ntp++) {
        int ro = warpN * 64 + ntp * 16 + ((lane >> 4) & 1) * 8 + (lane & 7);
        bAddr[ntp] = baseW + ro * (PW * 4) + ((lane >> 3) & 1) * 16;
    }

    for (int tile = blockIdx.x; tile < NTILES; tile += gridDim.x) {
        const int node0 = tile * 128;
        __syncthreads();
        if (FUSE_IN) {
            for (int i = tid; i < 640; i += 256) {
                int gi = node0 * 5 + i;
                s_xin[i] = (gi < NN * 5) ? x[gi] : 0.f;
            }
            __syncthreads();
        }
        {
            const int row = tid >> 1;
            const int ch = (tid & 1) * 64;
            const int node = node0 + row;
            float x5[5];
            if (FUSE_IN) {
#pragma unroll
                for (int k = 0; k < 5; k++) x5[k] = s_xin[row * 5 + k];
            }
#pragma unroll 4
            for (int i = 0; i < 16; i++) {
                int col = ch + i * 4;
                float4 v;
                if (FUSE_IN) {
                    float c4[4];
#pragma unroll
                    for (int c = 0; c < 4; c++) {
                        float acc = s_bin[col + c];
#pragma unroll
                        for (int k = 0; k < 5; k++)
                            acc = fmaf(x5[k], s_win[(col + c) * 5 + k], acc);
                        c4[c] = fmaxf(acc, 0.f);
                    }
                    v = make_float4(c4[0], c4[1], c4[2], c4[3]);
                } else {
                    v = (node < NN) ? *reinterpret_cast<const float4*>(&g_agg[node * 128 + col])
                                    : make_float4(0.f, 0.f, 0.f, 0.f);
                    v.x = fmaxf(fmaf(v.x, s_sc[col + 0], s_sh[col + 0]), 0.f);
                    v.y = fmaxf(fmaf(v.y, s_sc[col + 1], s_sh[col + 1]), 0.f);
                    v.z = fmaxf(fmaf(v.z, s_sc[col + 2], s_sh[col + 2]), 0.f);
                    v.w = fmaxf(fmaf(v.w, s_sc[col + 3], s_sh[col + 3]), 0.f);
                }
                uint32_t h0, l0, h1, l1;
                split2(v.x, v.y, h0, l0);
                split2(v.z, v.w, h1, l1);
                int widx = row * PW + (col >> 1);
                *reinterpret_cast<uint2*>(&sAhi[widx]) = make_uint2(h0, h1);
                *reinterpret_cast<uint2*>(&sAlo[widx]) = make_uint2(l0, l1);
            }
        }
        __syncthreads();

        float acc[2][8][4];
#pragma unroll
        for (int mt = 0; mt < 2; mt++)
#pragma unroll
            for (int nt = 0; nt < 8; nt++)
#pragma unroll
                for (int i = 0; i < 4; i++) acc[mt][nt][i] = 0.f;

#pragma unroll
        for (int ks = 0; ks < 8; ks++) {
            const uint32_t ko = ks * 32;
            // B fragments via ldmatrix: 4 hi + 4 lo x4 loads -> 8 nt tiles
            uint32_t bh[8][2], bl[8][2];
#pragma unroll
            for (int ntp = 0; ntp < 4; ntp++) {
                LDSM_X4(bh[2 * ntp][0], bh[2 * ntp][1], bh[2 * ntp + 1][0], bh[2 * ntp + 1][1],
                        bAddr[ntp] + ko);
                LDSM_X4(bl[2 * ntp][0], bl[2 * ntp][1], bl[2 * ntp + 1][0], bl[2 * ntp + 1][1],
                        bAddr[ntp] + WLO + ko);
            }
#pragma unroll
            for (int mt = 0; mt < 2; mt++) {
                uint32_t ah0, ah1, ah2, ah3, al0, al1, al2, al3;
                LDSM_X4(ah0, ah1, ah2, ah3, aAddr[mt] + ko);
                LDSM_X4(al0, al1, al2, al3, aAddr[mt] + WLO + ko);
#pragma unroll
                for (int nt = 0; nt < 8; nt++) {
                    mma_bf16(acc[mt][nt], ah0, ah1, ah2, ah3, bh[nt][0], bh[nt][1]);
                    mma_bf16(acc[mt][nt], ah0, ah1, ah2, ah3, bl[nt][0], bl[nt][1]);
                    mma_bf16(acc[mt][nt], al0, al1, al2, al3, bh[nt][0], bh[nt][1]);
                }
            }
        }

        float ats[4][2], atd[4][2];
#pragma unroll
        for (int s2 = 0; s2 < 4; s2++) {
            ats[s2][0] = ats[s2][1] = 0.f;
            atd[s2][0] = atd[s2][1] = 0.f;
        }
#pragma unroll
        for (int mt = 0; mt < 2; mt++) {
            const int r0 = warpM * 32 + mt * 16 + g;
            const int na = node0 + r0, nb = node0 + r0 + 8;
#pragma unroll
            for (int nt = 0; nt < 8; nt++) {
                const int colb = warpN * 64 + nt * 8 + q * 2;
                const int hs = nt >> 2;
                const float* a4 = acc[mt][nt];
                ats[mt * 2 + 0][hs] += a4[0] * s_as[colb] + a4[1] * s_as[colb + 1];
                atd[mt * 2 + 0][hs] += a4[0] * s_ad[colb] + a4[1] * s_ad[colb + 1];
                ats[mt * 2 + 1][hs] += a4[2] * s_as[colb] + a4[3] * s_as[colb + 1];
                atd[mt * 2 + 1][hs] += a4[2] * s_ad[colb] + a4[3] * s_ad[colb + 1];
                if (na < NN)
                    *reinterpret_cast<__half2*>(&g_lin[na * 128 + colb]) =
                        __floats2half2_rn(a4[0], a4[1]);
                if (nb < NN)
                    *reinterpret_cast<__half2*>(&g_lin[nb * 128 + colb]) =
                        __floats2half2_rn(a4[2], a4[3]);
            }
        }
#pragma unroll
        for (int o = 1; o <= 2; o <<= 1) {
#pragma unroll
            for (int s2 = 0; s2 < 4; s2++) {
#pragma unroll
                for (int hs = 0; hs < 2; hs++) {
                    ats[s2][hs] += __shfl_xor_sync(0xffffffffu, ats[s2][hs], o);
                    atd[s2][hs] += __shfl_xor_sync(0xffffffffu, atd[s2][hs], o);
                }
            }
        }
        if (HEADS == 4) {
            if (q == 0) {
#pragma unroll
                for (int s2 = 0; s2 < 4; s2++) {
                    int row = warpM * 32 + s2 * 8 + g;
                    int node = node0 + row;
                    if (node < NN) {
#pragma unroll
                        for (int hs = 0; hs < 2; hs++) {
                            int h = warpN * 2 + hs;
                            g_ssrc[node * 4 + h] = ats[s2][hs];
                            g_sdst[node * 4 + h] = atd[s2][hs];
                        }
                    }
                }
            }
        } else {
            if (q == 0) {
#pragma unroll
                for (int s2 = 0; s2 < 4; s2++) {
                    int row = warpM * 32 + s2 * 8 + g;
                    s_red[0][row][warpN] = ats[s2][0] + ats[s2][1];
                    s_red[1][row][warpN] = atd[s2][0] + atd[s2][1];
                }
            }
            __syncthreads();
            if (tid < 128) {
                int node = node0 + tid;
                if (node < NN) {
                    g_ssrc[node] = s_red[0][tid][0] + s_red[0][tid][1];
                    g_sdst[node] = s_red[1][tid][0] + s_red[1][tid][1];
                }
            }
        }
    }
}

// ---------------- fused attention + aggregation + BN stats (R12 version) ----------------
template <int HEADS>
__global__ void k_attnagg(int slot) {
    __shared__ float bsum[128], bsum2[128];
    const int tid = threadIdx.x;
    if (tid < 128) {
        bsum[tid] = 0.f;
        bsum2[tid] = 0.f;
    }
    __syncthreads();

    const int w = (blockIdx.x * blockDim.x + tid) >> 5;
    const int lane = tid & 31;
    if (w < NN) {
        const int beg = g_rowptr[w];
        const int end = g_rowptr[w + 1];

        float4 sd;
        if (HEADS == 4) sd = *reinterpret_cast<const float4*>(&g_sdst[w * 4]);
        else sd.x = g_sdst[w];

        const int hd = lane >> 3;
        float4 sume = make_float4(0.f, 0.f, 0.f, 0.f);
        float4 acc = make_float4(0.f, 0.f, 0.f, 0.f);
        for (int base = beg; base < end; base += 32) {
            const int i = base + lane;
            int s = 0;
            float4 ev = make_float4(0.f, 0.f, 0.f, 0.f);
            if (i < end) {
                s = g_csrc[i];
                if (HEADS == 4) {
                    float4 vs = *reinterpret_cast<const float4*>(&g_ssrc[s * 4]);
                    float lx = vs.x + sd.x; lx = lx > 0.f ? lx : 0.2f * lx;
                    float ly = vs.y + sd.y; ly = ly > 0.f ? ly : 0.2f * ly;
                    float lz = vs.z + sd.z; lz = lz > 0.f ? lz : 0.2f * lz;
                    float lw = vs.w + sd.w; lw = lw > 0.f ? lw : 0.2f * lw;
                    ev.x = __expf(lx); ev.y = __expf(ly);
                    ev.z = __expf(lz); ev.w = __expf(lw);
                    sume.x += ev.x; sume.y += ev.y; sume.z += ev.z; sume.w += ev.w;
                } else {
                    float l = g_ssrc[s] + sd.x;
                    l = l > 0.f ? l : 0.2f * l;
                    ev.x = __expf(l);
                    sume.x += ev.x;
                }
            }
            const int cnt = min(32, end - base);
            for (int j = 0; j < cnt; j++) {
                int sj = __shfl_sync(0xffffffffu, s, j);
                float evh;
                if (HEADS == 4) {
                    float e0 = __shfl_sync(0xffffffffu, ev.x, j);
                    float e1 = __shfl_sync(0xffffffffu, ev.y, j);
                    float e2 = __shfl_sync(0xffffffffu, ev.z, j);
                    float e3 = __shfl_sync(0xffffffffu, ev.w, j);
                    evh = (hd == 0) ? e0 : (hd == 1) ? e1 : (hd == 2) ? e2 : e3;
                } else {
                    evh = __shfl_sync(0xffffffffu, ev.x, j);
                }
                uint2 raw = *reinterpret_cast<const uint2*>(&g_lin[sj * 128 + lane * 4]);
                float2 f01 = __half22float2(*reinterpret_cast<__half2*>(&raw.x));
                float2 f23 = __half22float2(*reinterpret_cast<__half2*>(&raw.y));
                acc.x = fmaf(evh, f01.x, acc.x);
                acc.y = fmaf(evh, f01.y, acc.y);
                acc.z = fmaf(evh, f23.x, acc.z);
                acc.w = fmaf(evh, f23.y, acc.w);
            }
        }
#pragma unroll
        for (int o = 16; o > 0; o >>= 1) {
            sume.x += __shfl_xor_sync(0xffffffffu, sume.x, o);
            if (HEADS == 4) {
                sume.y += __shfl_xor_sync(0xffffffffu, sume.y, o);
                sume.z += __shfl_xor_sync(0xffffffffu, sume.z, o);
                sume.w += __shfl_xor_sync(0xffffffffu, sume.w, o);
            }
        }
        float dh;
        if (HEADS == 4)
            dh = (hd == 0) ? sume.x : (hd == 1) ? sume.y : (hd == 2) ? sume.z : sume.w;
        else
            dh = sume.x;
        float inv = 1.f / (dh + 1e-16f);
        acc.x *= inv; acc.y *= inv; acc.z *= inv; acc.w *= inv;
        *reinterpret_cast<float4*>(&g_agg[w * 128 + lane * 4]) = acc;

        const int c0 = lane * 4;
        atomicAdd(&bsum[c0 + 0], acc.x);
        atomicAdd(&bsum[c0 + 1], acc.y);
        atomicAdd(&bsum[c0 + 2], acc.z);
        atomicAdd(&bsum[c0 + 3], acc.w);
        atomicAdd(&bsum2[c0 + 0], acc.x * acc.x);
        atomicAdd(&bsum2[c0 + 1], acc.y * acc.y);
        atomicAdd(&bsum2[c0 + 2], acc.z * acc.z);
        atomicAdd(&bsum2[c0 + 3], acc.w * acc.w);
    }
    __syncthreads();
    if (tid < 128) {
        atomicAdd(&g_bnsum[slot * 128 + tid], bsum[tid]);
        atomicAdd(&g_bnsum2[slot * 128 + tid], bsum2[tid]);
    }
}

// ---------------- fused MLP head (+ resets g_cnt for next call) ----------------
__global__ void k_mlp(const float* __restrict__ W1, const float* __restrict__ b1,
                      const float* __restrict__ W2, const float* __restrict__ b2,
                      const float* __restrict__ gam, const float* __restrict__ bet,
                      float* __restrict__ out) {
    __shared__ float sW[64 * 129];
    __shared__ float sx[128 * 8];
    __shared__ float s_sc[128], s_sh[128];
    __shared__ float s_part[2][8];
    const int tid = threadIdx.x;  // 64
    const int wrp = tid >> 5, lane = tid & 31;
    for (int i = blockIdx.x * 64 + tid; i < NN; i += gridDim.x * 64) g_cnt[i] = 0;
    for (int idx = tid; idx < 64 * 128; idx += 64) {
        int t = idx >> 7, k = idx & 127;
        sW[t * 129 + k] = W1[idx];
    }
    for (int idx = tid; idx < 128; idx += 64) {
        float mu = g_bnsum[2 * 128 + idx] * (1.f / NN);
        float var = g_bnsum2[2 * 128 + idx] * (1.f / NN) - mu * mu;
        float sc = gam[idx] * rsqrtf(var + 1e-5f);
        s_sc[idx] = sc;
        s_sh[idx] = bet[idx] - mu * sc;
    }
    const float bias = b1[tid];
    const float w2 = W2[tid];
    const float b2v = b2[0];
    __syncthreads();
    const int NCH = NN / 8;
    for (int chunk = blockIdx.x; chunk < NCH; chunk += gridDim.x) {
        const int n0 = chunk * 8;
        __syncthreads();
#pragma unroll
        for (int nb = 0; nb < 8; nb++)
            for (int k = tid; k < 128; k += 64)
                sx[k * 8 + nb] = fmaf(g_agg[(n0 + nb) * 128 + k], s_sc[k], s_sh[k]);
        __syncthreads();
        float acc[8];
#pragma unroll
        for (int i = 0; i < 8; i++) acc[i] = 0.f;
#pragma unroll 4
        for (int k = 0; k < 128; k++) {
            float w = sW[tid * 129 + k];
            float4 xa = *reinterpret_cast<float4*>(&sx[k * 8]);
            float4 xb = *reinterpret_cast<float4*>(&sx[k * 8 + 4]);
            acc[0] = fmaf(w, xa.x, acc[0]);
            acc[1] = fmaf(w, xa.y, acc[1]);
            acc[2] = fmaf(w, xa.z, acc[2]);
            acc[3] = fmaf(w, xa.w, acc[3]);
            acc[4] = fmaf(w, xb.x, acc[4]);
            acc[5] = fmaf(w, xb.y, acc[5]);
            acc[6] = fmaf(w, xb.z, acc[6]);
            acc[7] = fmaf(w, xb.w, acc[7]);
        }
        float c8[8];
#pragma unroll
        for (int nb = 0; nb < 8; nb++) c8[nb] = fmaxf(acc[nb] + bias, 0.f) * w2;
#pragma unroll
        for (int o = 16; o > 0; o >>= 1)
#pragma unroll
            for (int nb = 0; nb < 8; nb++)
                c8[nb] += __shfl_xor_sync(0xffffffffu, c8[nb], o);
        if (lane == 0)
#pragma unroll
            for (int nb = 0; nb < 8; nb++) s_part[wrp][nb] = c8[nb];
        __syncthreads();
        if (tid < 8) out[n0 + tid] = s_part[0][tid] + s_part[1][tid] + b2v;
    }
}

// ---------------- launch ----------------
extern "C" void kernel_launch(void* const* d_in, const int* in_sizes, int n_in,
                              void* d_out, int out_size) {
    const float* x    = (const float*)d_in[0];
    const int*   ei   = (const int*)d_in[1];
    const float* W_in = (const float*)d_in[2];
    const float* b_in = (const float*)d_in[3];
    const float* Wl[3]  = {(const float*)d_in[4], (const float*)d_in[8], (const float*)d_in[12]};
    const float* ASl[3] = {(const float*)d_in[5], (const float*)d_in[9], (const float*)d_in[13]};
    const float* ADl[3] = {(const float*)d_in[6], (const float*)d_in[10], (const float*)d_in[14]};
    // GAT biases b0/b1/b2 cancel exactly in the following BatchNorm
    const float* Gl[3]  = {(const float*)d_in[16], (const float*)d_in[18], (const float*)d_in[20]};
    const float* Bl[3]  = {(const float*)d_in[17], (const float*)d_in[19], (const float*)d_in[21]};
    const float* Wc1 = (const float*)d_in[22];
    const float* bc1 = (const float*)d_in[23];
    const float* Wc2 = (const float*)d_in[24];
    const float* bc2 = (const float*)d_in[25];
    float* out = (float*)d_out;

    cudaFuncSetAttribute(k_gemm_tc<4, true>, cudaFuncAttributeMaxDynamicSharedMemorySize, GSMEM_BYTES);
    cudaFuncSetAttribute(k_gemm_tc<4, false>, cudaFuncAttributeMaxDynamicSharedMemorySize, GSMEM_BYTES);
    cudaFuncSetAttribute(k_gemm_tc<1, false>, cudaFuncAttributeMaxDynamicSharedMemorySize, GSMEM_BYTES);

    const int EB = 256;
    const int EG = (ET + EB - 1) / EB;
    const int HG = (NE + EB - 1) / EB;
    const int AGG_BLOCKS = NN * 32 / EB;  // 6250

    k_hist<<<HG, EB>>>(ei);
    k_scan<<<1, 1024>>>();
    k_scatter<<<EG, EB>>>(ei);

    // layer 0 (input layer fused; zeroes BN slot 0)
    k_gemm_tc<4, true><<<148, 256, GSMEM_BYTES>>>(Wl[0], ASl[0], ADl[0], x, W_in, b_in,
                                                  nullptr, nullptr, 0, 0);
    k_attnagg<4><<<AGG_BLOCKS, EB>>>(0);
    // layer 1 (reads BN slot 0; zeroes slot 1)
    k_gemm_tc<4, false><<<148, 256, GSMEM_BYTES>>>(Wl[1], ASl[1], ADl[1], x, W_in, b_in,
                                                   Gl[0], Bl[0], 0, 1);
    k_attnagg<4><<<AGG_BLOCKS, EB>>>(1);
    // layer 2 (reads slot 1; zeroes slot 2)
    k_gemm_tc<1, false><<<148, 256, GSMEM_BYTES>>>(Wl[2], ASl[2], ADl[2], x, W_in, b_in,
                                                   Gl[1], Bl[1], 1, 2);
    k_attnagg<1><<<AGG_BLOCKS, EB>>>(2);
    // fused MLP head (reads slot 2; resets g_cnt for next call)
    k_mlp<<<1024, 64>>>(Wc1, bc1, Wc2, bc2, Gl[2], Bl[2], out);
}